// round 5
// baseline (speedup 1.0000x reference)
#include <cuda_runtime.h>

// Thole dipole-dipole interaction tensor.
//   t[e] = 3*lambda5*inv_r5 * v v^T  -  lambda3*inv_r3 * I3
// Inputs (metadata order): species(i32,N) [unused], edge_src(i32,E),
// edge_dst(i32,E), distances(f32,E), vec(f32,3E), polarisability(f32,N).
// Output: f32, E*9.
//
// HBM-bound: ~60B/edge -> ~384MB total; target is the DRAM roofline.
// - smem-staged vec loads + output stores -> fully coalesced 128-bit traffic
// - ITEMS=2 edges/thread doubles gather-chain MLP
// - streaming data uses evict-first (__ldcs/__stcs) so the 400KB pol array
//   stays L2-resident for the random gathers

#define BOHR_F 0.52917721067f
#define A_MUTUAL_F 0.39f

static constexpr int TPB   = 256;
static constexpr int ITEMS = 2;
static constexpr int EPB   = TPB * ITEMS;            // 512 edges per block

static constexpr int VEC_F4 = EPB * 3 / 4;           // 384 float4 staged vec
static constexpr int OUT_F4 = EPB * 9 / 4;           // 1152 float4 staged out

__global__ __launch_bounds__(TPB)
void polarisation_kernel(const int* __restrict__ edge_src,
                         const int* __restrict__ edge_dst,
                         const float* __restrict__ distances,
                         const float* __restrict__ vec,
                         const float* __restrict__ pol,
                         float* __restrict__ out,
                         int E) {
    __shared__ float4 s_vec4[VEC_F4];   // 6 KB
    __shared__ float4 s_out4[OUT_F4];   // 18 KB

    float* s_vec = (float*)s_vec4;
    float* s_out = (float*)s_out4;

    const int tid = threadIdx.x;
    const int block_start = blockIdx.x * EPB;

    // ---- Phase A: stage vec[block_start*3 .. +EPB*3) via 128-bit loads ----
    {
        const int vbase4 = block_start * 3 / 4;      // float4 base (EPB*3 % 4 == 0)
        const int vlimit = E * 3;                    // float limit
        #pragma unroll
        for (int k = 0; k < (VEC_F4 + TPB - 1) / TPB; k++) {
            const int idx = tid + k * TPB;
            if (idx < VEC_F4) {
                const int gf = (vbase4 + idx) * 4;
                if (gf + 3 < vlimit) {
                    s_vec4[idx] = __ldcs(&((const float4*)vec)[vbase4 + idx]);
                } else {
                    #pragma unroll
                    for (int j = 0; j < 4; j++)
                        s_vec[idx * 4 + j] = (gf + j < vlimit) ? __ldcs(&vec[gf + j]) : 0.0f;
                }
            }
        }
    }
    __syncthreads();

    // ---- Phase B: compute ITEMS edges per thread (strided by TPB) ----
    {
        const float inv_bohr = 1.0f / BOHR_F;
        const float inv_b6 = inv_bohr * inv_bohr * inv_bohr *
                             inv_bohr * inv_bohr * inv_bohr;

        #pragma unroll
        for (int k = 0; k < ITEMS; k++) {
            const int le = tid + k * TPB;            // local edge in [0, EPB)
            const int e  = block_start + le;
            if (e < E) {
                const float r = __ldcs(&distances[e]) * inv_bohr;
                // stride-3 smem reads: gcd(3,32)=1 -> conflict-free
                const float vx = s_vec[le * 3 + 0] * inv_bohr;
                const float vy = s_vec[le * 3 + 1] * inv_bohr;
                const float vz = s_vec[le * 3 + 2] * inv_bohr;

                const int si = __ldcs(&edge_src[e]);
                const int di = __ldcs(&edge_dst[e]);
                // pol is 400 KB -> keep L2-resident (normal policy, not streamed)
                const float alpha_ij = __ldg(&pol[si]) * __ldg(&pol[di]) * inv_b6;

                const float inv_r  = __fdividef(1.0f, r);
                const float inv_r2 = inv_r * inv_r;
                const float inv_r3 = inv_r2 * inv_r;
                const float inv_r5 = inv_r3 * inv_r2;

                // a*u^3 = a * r^3 / sqrt(alpha_ij)  (== a*(r/alpha^(1/6))^3)
                const float r3  = r * r * r;
                const float au3 = A_MUTUAL_F * r3 * rsqrtf(alpha_ij);
                const float ex  = __expf(-au3);
                const float lambda3 = 1.0f - ex;
                const float lambda5 = 1.0f - (1.0f + au3) * ex;

                const float c5 = 3.0f * lambda5 * inv_r5;
                const float c3 = lambda3 * inv_r3;

                // stride-9 smem writes: gcd(9,32)=1 -> conflict-free
                float* o = &s_out[le * 9];
                o[0] = c5 * vx * vx - c3;
                o[1] = c5 * vx * vy;
                o[2] = c5 * vx * vz;
                o[3] = c5 * vy * vx;
                o[4] = c5 * vy * vy - c3;
                o[5] = c5 * vy * vz;
                o[6] = c5 * vz * vx;
                o[7] = c5 * vz * vy;
                o[8] = c5 * vz * vz - c3;
            }
        }
    }
    __syncthreads();

    // ---- Phase C: coalesced 128-bit evict-first stores of EPB*9 floats ----
    {
        const long long obase4 = (long long)block_start * 9 / 4; // float4 base
        const long long olimit = (long long)E * 9;               // float limit
        #pragma unroll
        for (int k = 0; k < (OUT_F4 + TPB - 1) / TPB; k++) {
            const int idx = tid + k * TPB;
            if (idx < OUT_F4) {
                const long long gf = (obase4 + idx) * 4;
                if (gf + 3 < olimit) {
                    __stcs(&((float4*)out)[obase4 + idx], s_out4[idx]);
                } else {
                    #pragma unroll
                    for (int j = 0; j < 4; j++)
                        if (gf + j < olimit) __stcs(&out[gf + j], s_out[idx * 4 + j]);
                }
            }
        }
    }
}

extern "C" void kernel_launch(void* const* d_in, const int* in_sizes, int n_in,
                              void* d_out, int out_size) {
    // metadata order: species, edge_src, edge_dst, distances, vec, polarisability
    const int*   edge_src = (const int*)d_in[1];
    const int*   edge_dst = (const int*)d_in[2];
    const float* dist     = (const float*)d_in[3];
    const float* vec      = (const float*)d_in[4];
    const float* pol      = (const float*)d_in[5];
    float* out = (float*)d_out;

    const int E = in_sizes[1];
    const int blocks = (E + EPB - 1) / EPB;
    polarisation_kernel<<<blocks, TPB>>>(edge_src, edge_dst, dist, vec, pol, out, E);
}